// round 16
// baseline (speedup 1.0000x reference)
#include <cuda_runtime.h>
#include <cuda_fp16.h>
#include <cstdint>

#define NN 50000
#define DD 128
#define EE 800000
#define EPSL 1e-5f

#define SCH 512
#define SNB ((NN + SCH - 1) / SCH)   // 98

// GEMM tiling (fp16 MMA, full-K resident, persistent 2 tiles/block)
#define BM 128
#define APH 136                       // As row stride in halves (272B rows)
#define WPH 136                       // Ws row stride in halves
#define SMEM_BYTES ((BM * APH + DD * WPH) * 2)   // 69632 B
#define GEMM_GRID 296                 // 2 blocks/SM x 148 SMs, single wave
#define NTILES ((NN + BM - 1) / BM)   // 391

// ---------------- scratch (device globals; no allocation allowed) -------------
__device__ float  g_dinv[NN];
__device__ __half g_tmpA[NN * DD];    // fp16 messages: dinv[i]*(ReLU(LN(h))@W)
__device__ __half g_tmpB[NN * DD];
__device__ float  g_x1[NN * DD];      // x after layer0 + residual
__device__ float  g_h2[NN * DD];      // layer1 output
__device__ __half g_W16[3 * DD * DD]; // fp16 weights (pre-converted, 3 matrices)
__device__ int    g_cnt[NN];
__device__ int    g_start[NN];
__device__ int    g_cursor[NN];
__device__ int    g_esrc[EE];
__device__ int    g_csum[SNB];

// ---------------- prep0: weight fp16 conversion + cnt zero (merged) ------------
__global__ void k_prep0(const float* __restrict__ W0, const float* __restrict__ W1,
                        const float* __restrict__ W2) {
    int idx = blockIdx.x * blockDim.x + threadIdx.x;
    if (idx < 3 * DD * DD / 4) {
        int which = idx / (DD * DD / 4);
        int i = idx % (DD * DD / 4);
        const float* W = (which == 0) ? W0 : (which == 1) ? W1 : W2;
        float4 wv = ((const float4*)W)[i];
        __half2 p0 = __floats2half2_rn(wv.x, wv.y);
        __half2 p1 = __floats2half2_rn(wv.z, wv.w);
        uint2 u;
        u.x = *(uint32_t*)&p0;
        u.y = *(uint32_t*)&p1;
        ((uint2*)g_W16)[idx] = u;
    }
    if (idx < NN) g_cnt[idx] = 0;
}

// ---------------- CSR build ----------------------------------------------------
__global__ void k_hist(const int* __restrict__ dst) {
    int e = blockIdx.x * blockDim.x + threadIdx.x;
    if (e < EE) atomicAdd(&g_cnt[dst[e]], 1);
}

// per-chunk sums + dinv (folded)
__global__ void __launch_bounds__(SCH) k_scan_a() {
    __shared__ int sm[SCH];
    int t = threadIdx.x;
    int i = blockIdx.x * SCH + t;
    int v = (i < NN) ? g_cnt[i] : 0;
    sm[t] = v;
    if (i < NN) g_dinv[i] = rsqrtf(1.0f + (float)v);
    __syncthreads();
    for (int off = SCH / 2; off > 0; off >>= 1) {
        if (t < off) sm[t] += sm[t + off];
        __syncthreads();
    }
    if (t == 0) g_csum[blockIdx.x] = sm[0];
}

__global__ void __launch_bounds__(SCH) k_scan_c() {
    __shared__ int sm[SCH];
    __shared__ int base;
    int t = threadIdx.x;
    int i = blockIdx.x * SCH + t;
    int v = (i < NN) ? g_cnt[i] : 0;
    sm[t] = v;
    if (t == 0) {
        int run = 0;
        for (int j = 0; j < blockIdx.x; j++) run += g_csum[j];
        base = run;
    }
    __syncthreads();
    for (int off = 1; off < SCH; off <<= 1) {
        int x = (t >= off) ? sm[t - off] : 0;
        __syncthreads();
        sm[t] += x;
        __syncthreads();
    }
    if (i < NN) {
        int excl = sm[t] - v + base;
        g_start[i] = excl;
        g_cursor[i] = excl;
    }
}

__global__ void k_bucket(const int* __restrict__ src, const int* __restrict__ dst) {
    int e = blockIdx.x * blockDim.x + threadIdx.x;
    if (e < EE) {
        int pos = atomicAdd(&g_cursor[dst[e]], 1);
        g_esrc[pos] = src[e];
    }
}

// ---------------- MMA helpers ---------------------------------------------------
__device__ __forceinline__ uint32_t smem_u32(const void* p) {
    return (uint32_t)__cvta_generic_to_shared(p);
}

__device__ __forceinline__ void ldmatrix_x4(uint32_t& r0, uint32_t& r1,
                                            uint32_t& r2, uint32_t& r3, uint32_t addr) {
    asm volatile("ldmatrix.sync.aligned.m8n8.x4.shared.b16 {%0,%1,%2,%3}, [%4];"
                 : "=r"(r0), "=r"(r1), "=r"(r2), "=r"(r3) : "r"(addr));
}

__device__ __forceinline__ void ldmatrix_x2_trans(uint32_t& r0, uint32_t& r1, uint32_t addr) {
    asm volatile("ldmatrix.sync.aligned.m8n8.x2.trans.shared.b16 {%0,%1}, [%2];"
                 : "=r"(r0), "=r"(r1) : "r"(addr));
}

__device__ __forceinline__ void mma_f16(float4& c, uint32_t a0, uint32_t a1,
                                        uint32_t a2, uint32_t a3,
                                        uint32_t b0, uint32_t b1) {
    asm volatile("mma.sync.aligned.m16n8k16.row.col.f32.f16.f16.f32 "
                 "{%0,%1,%2,%3}, {%4,%5,%6,%7}, {%8,%9}, {%0,%1,%2,%3};"
                 : "+f"(c.x), "+f"(c.y), "+f"(c.z), "+f"(c.w)
                 : "r"(a0), "r"(a1), "r"(a2), "r"(a3), "r"(b0), "r"(b1));
}

// ---------------- fused LN + ReLU + fp16 GEMM + dinv prescale ------------------
// tout[i] = half( dinv[i] * ( ReLU( LN(h_i)*g + bt ) @ W ) )
// Block 512 thr (16 warps); persistent: tiles bid and bid+GEMM_GRID.
// W staged once, reused across both tiles.
__global__ void __launch_bounds__(512) k_ln_gemm(const float* __restrict__ h,
                          const float* __restrict__ g,
                          const float* __restrict__ bt,
                          const __half* __restrict__ W16,
                          __half* __restrict__ tout) {
    extern __shared__ __half smh[];
    __half* As = smh;                 // [BM][APH] halves
    __half* Ws = smh + BM * APH;      // [DD][WPH] halves

    int tid = threadIdx.x;
    int lane = tid & 31;
    int w = tid >> 5;           // 0..15
    int qid = lane >> 2;        // 0..7
    int tq = lane & 3;          // 0..3

    // --- stage full W (fp16, 32KB) -> Ws (once) ---
    for (int idx = tid; idx < DD * DD / 8; idx += 512) {
        int kk = idx >> 4;            // 16 uint4 per row
        int c8 = (idx & 15) * 8;
        uint4 u = ((const uint4*)W16)[idx];
        *(uint4*)(Ws + kk * WPH + c8) = u;
    }

    // warp tile: warp_m 0..3 (m32), warp_n 0..3 (n32)
    int warp_m = w & 3;
    int warp_n = w >> 2;
    int m0 = warp_m * 32;
    int nb = warp_n * 32;

    // ldmatrix lane addressing
    int a_row = (lane & 7) + 8 * ((lane >> 3) & 1);
    int a_col8 = 8 * (lane >> 4);
    int b_row = lane & 15;

    float4 gg = ((const float4*)g)[lane];
    float4 bbln = ((const float4*)bt)[lane];

    #pragma unroll 1
    for (int tile = blockIdx.x; tile < NTILES; tile += GEMM_GRID) {
        int row0 = tile * BM;

        __syncthreads();   // Ws ready (1st tile) / prior tile's As reads done

        // --- LN + ReLU -> fp16 As; warp w handles rows w, w+16, ..., w+112 ---
        for (int r = w; r < BM; r += 16) {
            int row = row0 + r;
            float4 v = make_float4(0.f, 0.f, 0.f, 0.f);
            if (row < NN) v = ((const float4*)(h + (size_t)row * DD))[lane];
            float s = v.x + v.y + v.z + v.w;
            #pragma unroll
            for (int o = 16; o; o >>= 1) s += __shfl_xor_sync(0xffffffffu, s, o);
            float mu = s * (1.0f / DD);
            float dx = v.x - mu, dy = v.y - mu, dz = v.z - mu, dw = v.w - mu;
            float q = dx * dx + dy * dy + dz * dz + dw * dw;
            #pragma unroll
            for (int o = 16; o; o >>= 1) q += __shfl_xor_sync(0xffffffffu, q, o);
            float rstd = rsqrtf(q * (1.0f / DD) + EPSL);
            __half2 h2a = __floats2half2_rn(fmaxf(fmaf(dx * rstd, gg.x, bbln.x), 0.f),
                                            fmaxf(fmaf(dy * rstd, gg.y, bbln.y), 0.f));
            __half2 h2b = __floats2half2_rn(fmaxf(fmaf(dz * rstd, gg.z, bbln.z), 0.f),
                                            fmaxf(fmaf(dw * rstd, gg.w, bbln.w), 0.f));
            uint2 u;
            u.x = *(uint32_t*)&h2a;
            u.y = *(uint32_t*)&h2b;
            *(uint2*)(As + r * APH + lane * 4) = u;
        }

        __syncthreads();

        float4 c[2][4];
        #pragma unroll
        for (int mt = 0; mt < 2; mt++)
            #pragma unroll
            for (int nt = 0; nt < 4; nt++) c[mt][nt] = make_float4(0.f, 0.f, 0.f, 0.f);

        #pragma unroll
        for (int ks = 0; ks < DD / 16; ks++) {
            int kb = ks * 16;
            uint32_t a[2][4];
            #pragma unroll
            for (int mt = 0; mt < 2; mt++) {
                uint32_t addr = smem_u32(As + (m0 + mt * 16 + a_row) * APH + kb + a_col8);
                ldmatrix_x4(a[mt][0], a[mt][1], a[mt][2], a[mt][3], addr);
            }
            uint32_t b[4][2];
            #pragma unroll
            for (int nt = 0; nt < 4; nt++) {
                int nbf = nb + nt * 8;
                uint32_t addr = smem_u32(Ws + (kb + b_row) * WPH + nbf);
                ldmatrix_x2_trans(b[nt][0], b[nt][1], addr);
            }
            #pragma unroll
            for (int mt = 0; mt < 2; mt++)
                #pragma unroll
                for (int nt = 0; nt < 4; nt++)
                    mma_f16(c[mt][nt], a[mt][0], a[mt][1], a[mt][2], a[mt][3],
                            b[nt][0], b[nt][1]);
        }

        // epilogue: scale by dinv[row], write half2 pairs
        #pragma unroll
        for (int mt = 0; mt < 2; mt++) {
            int ra = row0 + m0 + mt * 16 + qid;
            int rb = ra + 8;
            float dva = (ra < NN) ? g_dinv[ra] : 0.f;
            float dvb = (rb < NN) ? g_dinv[rb] : 0.f;
            #pragma unroll
            for (int nt = 0; nt < 4; nt++) {
                int col = nb + nt * 8 + 2 * tq;
                if (ra < NN) {
                    __half2 o = __floats2half2_rn(c[mt][nt].x * dva, c[mt][nt].y * dva);
                    *(uint32_t*)(tout + (size_t)ra * DD + col) = *(uint32_t*)&o;
                }
                if (rb < NN) {
                    __half2 o = __floats2half2_rn(c[mt][nt].z * dvb, c[mt][nt].w * dvb);
                    *(uint32_t*)(tout + (size_t)rb * DD + col) = *(uint32_t*)&o;
                }
            }
        }
    }
}

// ---------------- per-node gather accumulate (fp16 messages -> fp32 out) -------
// out[i] = b + dinv[i]*(tin[i] + sum_{e in CSR[i]} tin[src_e]) (+ res[i])
__global__ void __launch_bounds__(256) k_accum(const __half* __restrict__ tin,
                        float* __restrict__ out,
                        const float* __restrict__ b,
                        const float* __restrict__ res) {
    int node = (blockIdx.x * blockDim.x + threadIdx.x) >> 5;
    int lane = threadIdx.x & 31;
    if (node >= NN) return;

    const uint2* T = (const uint2*)tin;   // 4 halves per lane
    int s0 = g_start[node];
    int cnt = g_cnt[node];

    float4 a[8];
    {
        uint2 u = T[(size_t)node * 32 + lane];
        float2 f0 = __half22float2(*(__half2*)&u.x);
        float2 f1 = __half22float2(*(__half2*)&u.y);
        a[0] = make_float4(f0.x, f0.y, f1.x, f1.y);
    }
    #pragma unroll
    for (int j = 1; j < 8; j++) a[j] = make_float4(0.f, 0.f, 0.f, 0.f);

    int e = 0;
    for (; e + 8 <= cnt; e += 8) {
        int idx[8];
        #pragma unroll
        for (int j = 0; j < 8; j++) idx[j] = g_esrc[s0 + e + j];
        #pragma unroll
        for (int j = 0; j < 8; j++) {
            uint2 u = T[(size_t)idx[j] * 32 + lane];
            float2 f0 = __half22float2(*(__half2*)&u.x);
            float2 f1 = __half22float2(*(__half2*)&u.y);
            a[j].x += f0.x; a[j].y += f0.y; a[j].z += f1.x; a[j].w += f1.y;
        }
    }
    for (; e < cnt; e++) {
        int i0 = g_esrc[s0 + e];
        uint2 u = T[(size_t)i0 * 32 + lane];
        float2 f0 = __half22float2(*(__half2*)&u.x);
        float2 f1 = __half22float2(*(__half2*)&u.y);
        a[0].x += f0.x; a[0].y += f0.y; a[0].z += f1.x; a[0].w += f1.y;
    }
    #pragma unroll
    for (int j = 1; j < 8; j++) {
        a[0].x += a[j].x; a[0].y += a[j].y; a[0].z += a[j].z; a[0].w += a[j].w;
    }

    float dv = g_dinv[node];
    float4 bb = ((const float4*)b)[lane];
    float4 o;
    o.x = fmaf(dv, a[0].x, bb.x);
    o.y = fmaf(dv, a[0].y, bb.y);
    o.z = fmaf(dv, a[0].z, bb.z);
    o.w = fmaf(dv, a[0].w, bb.w);
    if (res) {
        float4 r = ((const float4*)(res))[(size_t)node * 32 + lane];
        o.x += r.x; o.y += r.y; o.z += r.z; o.w += r.w;
    }
    ((float4*)out)[(size_t)node * 32 + lane] = o;
}

// ---------------- launch ------------------------------------------------------
extern "C" void kernel_launch(void* const* d_in, const int* in_sizes, int n_in,
                              void* d_out, int out_size) {
    const float* x   = (const float*)d_in[0];
    const int*   ei  = (const int*)d_in[1];
    const int*   src = ei;
    const int*   dst = ei + EE;
    const float* lng0 = (const float*)d_in[2];
    const float* lnb0 = (const float*)d_in[3];
    const float* W0   = (const float*)d_in[4];
    const float* b0   = (const float*)d_in[5];
    const float* lng1 = (const float*)d_in[6];
    const float* lnb1 = (const float*)d_in[7];
    const float* W1   = (const float*)d_in[8];
    const float* b1   = (const float*)d_in[9];
    const float* lng2 = (const float*)d_in[10];
    const float* lnb2 = (const float*)d_in[11];
    const float* W2   = (const float*)d_in[12];
    const float* b2   = (const float*)d_in[13];
    float* out = (float*)d_out;

    __half* d_tA; cudaGetSymbolAddress((void**)&d_tA, g_tmpA);
    __half* d_tB; cudaGetSymbolAddress((void**)&d_tB, g_tmpB);
    float*  d_x1; cudaGetSymbolAddress((void**)&d_x1, g_x1);
    float*  d_h2; cudaGetSymbolAddress((void**)&d_h2, g_h2);
    __half* d_W16base; cudaGetSymbolAddress((void**)&d_W16base, g_W16);
    __half* d_Wa = d_W16base;
    __half* d_Wb = d_W16base + DD * DD;
    __half* d_Wc = d_W16base + 2 * DD * DD;

    cudaFuncSetAttribute(k_ln_gemm, cudaFuncAttributeMaxDynamicSharedMemorySize, SMEM_BYTES);

    const int acc_blocks = (NN * 32 + 255) / 256;

    // prep: weights + zero (merged), hist, dinv+chunk sums
    k_prep0<<<(NN + 255) / 256, 256>>>(W0, W1, W2);
    k_hist<<<(EE + 255) / 256, 256>>>(dst);
    k_scan_a<<<SNB, SCH>>>();

    // layer 0 GEMM (launch #4 -> ncu profile slot): x -> tA
    k_ln_gemm<<<GEMM_GRID, 512, SMEM_BYTES>>>(x, lng0, lnb0, d_Wa, d_tA);

    // prep part 2 (CSR for accum)
    k_scan_c<<<SNB, SCH>>>();
    k_bucket<<<(EE + 255) / 256, 256>>>(src, dst);

    // layer 0 accum: tA (+x) -> x1
    k_accum<<<acc_blocks, 256>>>(d_tA, d_x1, b0, x);

    // layer 1: x1 -> tB ; accum -> h2
    k_ln_gemm<<<GEMM_GRID, 512, SMEM_BYTES>>>(d_x1, lng1, lnb1, d_Wb, d_tB);
    k_accum<<<acc_blocks, 256>>>(d_tB, d_h2, b1, nullptr);

    // layer 2: h2 -> tA ; accum (+x1) -> out
    k_ln_gemm<<<GEMM_GRID, 512, SMEM_BYTES>>>(d_h2, lng2, lnb2, d_Wc, d_tA);
    k_accum<<<acc_blocks, 256>>>(d_tA, out, b2, d_x1);
}

// round 17
// speedup vs baseline: 1.4431x; 1.4431x over previous
#include <cuda_runtime.h>
#include <cuda_fp16.h>
#include <cstdint>

#define NN 50000
#define DD 128
#define EE 800000
#define EPSL 1e-5f

#define SCH 512
#define SNB ((NN + SCH - 1) / SCH)   // 98

// GEMM tiling (fp16 MMA, full-K resident)
#define BM 128
#define APH 136                       // As row stride in halves (272B rows)
#define WPH 136                       // Ws row stride in halves
#define SMEM_BYTES ((BM * APH + DD * WPH) * 2)   // 69632 B

// ---------------- scratch (device globals; no allocation allowed) -------------
__device__ float  g_dinv[NN];
__device__ __half g_tmpA[NN * DD];    // fp16 messages: dinv[i]*(ReLU(LN(h))@W)
__device__ __half g_tmpB[NN * DD];
__device__ float  g_x1[NN * DD];      // x after layer0 + residual
__device__ float  g_h2[NN * DD];      // layer1 output
__device__ __half g_W16[3 * DD * DD]; // fp16 weights (pre-converted, 3 matrices)
__device__ int    g_cnt[NN];
__device__ int    g_start[NN];
__device__ int    g_cursor[NN];
__device__ int    g_esrc[EE];
__device__ int    g_csum[SNB];

// ---------------- prep0: weight fp16 conversion + cnt zero (merged) ------------
__global__ void k_prep0(const float* __restrict__ W0, const float* __restrict__ W1,
                        const float* __restrict__ W2) {
    int idx = blockIdx.x * blockDim.x + threadIdx.x;
    if (idx < 3 * DD * DD / 4) {
        int which = idx / (DD * DD / 4);
        int i = idx % (DD * DD / 4);
        const float* W = (which == 0) ? W0 : (which == 1) ? W1 : W2;
        float4 wv = ((const float4*)W)[i];
        __half2 p0 = __floats2half2_rn(wv.x, wv.y);
        __half2 p1 = __floats2half2_rn(wv.z, wv.w);
        uint2 u;
        u.x = *(uint32_t*)&p0;
        u.y = *(uint32_t*)&p1;
        ((uint2*)g_W16)[idx] = u;
    }
    if (idx < NN) g_cnt[idx] = 0;
}

// ---------------- CSR build ----------------------------------------------------
__global__ void k_hist(const int* __restrict__ dst) {
    int e = blockIdx.x * blockDim.x + threadIdx.x;
    if (e < EE) atomicAdd(&g_cnt[dst[e]], 1);
}

// per-chunk sums + dinv (folded)
__global__ void __launch_bounds__(SCH) k_scan_a() {
    __shared__ int sm[SCH];
    int t = threadIdx.x;
    int i = blockIdx.x * SCH + t;
    int v = (i < NN) ? g_cnt[i] : 0;
    sm[t] = v;
    if (i < NN) g_dinv[i] = rsqrtf(1.0f + (float)v);
    __syncthreads();
    for (int off = SCH / 2; off > 0; off >>= 1) {
        if (t < off) sm[t] += sm[t + off];
        __syncthreads();
    }
    if (t == 0) g_csum[blockIdx.x] = sm[0];
}

__global__ void __launch_bounds__(SCH) k_scan_c() {
    __shared__ int sm[SCH];
    __shared__ int base;
    int t = threadIdx.x;
    int i = blockIdx.x * SCH + t;
    int v = (i < NN) ? g_cnt[i] : 0;
    sm[t] = v;
    if (t == 0) {
        int run = 0;
        for (int j = 0; j < blockIdx.x; j++) run += g_csum[j];
        base = run;
    }
    __syncthreads();
    for (int off = 1; off < SCH; off <<= 1) {
        int x = (t >= off) ? sm[t - off] : 0;
        __syncthreads();
        sm[t] += x;
        __syncthreads();
    }
    if (i < NN) {
        int excl = sm[t] - v + base;
        g_start[i] = excl;
        g_cursor[i] = excl;
    }
}

__global__ void k_bucket(const int* __restrict__ src, const int* __restrict__ dst) {
    int e = blockIdx.x * blockDim.x + threadIdx.x;
    if (e < EE) {
        int pos = atomicAdd(&g_cursor[dst[e]], 1);
        g_esrc[pos] = src[e];
    }
}

// ---------------- MMA helpers ---------------------------------------------------
__device__ __forceinline__ uint32_t smem_u32(const void* p) {
    return (uint32_t)__cvta_generic_to_shared(p);
}

__device__ __forceinline__ void ldmatrix_x4(uint32_t& r0, uint32_t& r1,
                                            uint32_t& r2, uint32_t& r3, uint32_t addr) {
    asm volatile("ldmatrix.sync.aligned.m8n8.x4.shared.b16 {%0,%1,%2,%3}, [%4];"
                 : "=r"(r0), "=r"(r1), "=r"(r2), "=r"(r3) : "r"(addr));
}

__device__ __forceinline__ void ldmatrix_x2_trans(uint32_t& r0, uint32_t& r1, uint32_t addr) {
    asm volatile("ldmatrix.sync.aligned.m8n8.x2.trans.shared.b16 {%0,%1}, [%2];"
                 : "=r"(r0), "=r"(r1) : "r"(addr));
}

__device__ __forceinline__ void mma_f16(float4& c, uint32_t a0, uint32_t a1,
                                        uint32_t a2, uint32_t a3,
                                        uint32_t b0, uint32_t b1) {
    asm volatile("mma.sync.aligned.m16n8k16.row.col.f32.f16.f16.f32 "
                 "{%0,%1,%2,%3}, {%4,%5,%6,%7}, {%8,%9}, {%0,%1,%2,%3};"
                 : "+f"(c.x), "+f"(c.y), "+f"(c.z), "+f"(c.w)
                 : "r"(a0), "r"(a1), "r"(a2), "r"(a3), "r"(b0), "r"(b1));
}

// ---------------- fused LN + ReLU + fp16 GEMM + dinv prescale ------------------
// tout[i] = half( dinv[i] * ( ReLU( LN(h_i)*g + bt ) @ W ) )
// Block 512 thr (16 warps); tile M=128 x N=128; warp tile m32 x n32.
// (R15 body verbatim — known regs=58, 2 blocks/SM.)
__global__ void __launch_bounds__(512) k_ln_gemm(const float* __restrict__ h,
                          const float* __restrict__ g,
                          const float* __restrict__ bt,
                          const __half* __restrict__ W16,
                          __half* __restrict__ tout) {
    extern __shared__ __half smh[];
    __half* As = smh;                 // [BM][APH] halves
    __half* Ws = smh + BM * APH;      // [DD][WPH] halves

    int tid = threadIdx.x;
    int lane = tid & 31;
    int w = tid >> 5;           // 0..15
    int qid = lane >> 2;        // 0..7
    int tq = lane & 3;          // 0..3
    int row0 = blockIdx.x * BM;

    // --- stage full W (fp16, 32KB) -> Ws ---
    for (int idx = tid; idx < DD * DD / 8; idx += 512) {
        int kk = idx >> 4;            // 16 uint4 per row
        int c8 = (idx & 15) * 8;
        uint4 u = ((const uint4*)W16)[idx];
        *(uint4*)(Ws + kk * WPH + c8) = u;
    }

    // --- LN + ReLU -> fp16 As; warp w handles rows w, w+16, ..., w+112 ---
    for (int r = w; r < BM; r += 16) {
        int row = row0 + r;
        float4 v = make_float4(0.f, 0.f, 0.f, 0.f);
        if (row < NN) v = ((const float4*)(h + (size_t)row * DD))[lane];
        float s = v.x + v.y + v.z + v.w;
        #pragma unroll
        for (int o = 16; o; o >>= 1) s += __shfl_xor_sync(0xffffffffu, s, o);
        float mu = s * (1.0f / DD);
        float dx = v.x - mu, dy = v.y - mu, dz = v.z - mu, dw = v.w - mu;
        float q = dx * dx + dy * dy + dz * dz + dw * dw;
        #pragma unroll
        for (int o = 16; o; o >>= 1) q += __shfl_xor_sync(0xffffffffu, q, o);
        float rstd = rsqrtf(q * (1.0f / DD) + EPSL);
        float4 gg = ((const float4*)g)[lane];
        float4 bb = ((const float4*)bt)[lane];
        __half2 h2a = __floats2half2_rn(fmaxf(fmaf(dx * rstd, gg.x, bb.x), 0.f),
                                        fmaxf(fmaf(dy * rstd, gg.y, bb.y), 0.f));
        __half2 h2b = __floats2half2_rn(fmaxf(fmaf(dz * rstd, gg.z, bb.z), 0.f),
                                        fmaxf(fmaf(dw * rstd, gg.w, bb.w), 0.f));
        uint2 u;
        u.x = *(uint32_t*)&h2a;
        u.y = *(uint32_t*)&h2b;
        *(uint2*)(As + r * APH + lane * 4) = u;
    }

    __syncthreads();   // the only barrier

    // warp tile: warp_m 0..3 (m32), warp_n 0..3 (n32)
    int warp_m = w & 3;
    int warp_n = w >> 2;
    int m0 = warp_m * 32;
    int nb = warp_n * 32;

    float4 c[2][4];
    #pragma unroll
    for (int mt = 0; mt < 2; mt++)
        #pragma unroll
        for (int nt = 0; nt < 4; nt++) c[mt][nt] = make_float4(0.f, 0.f, 0.f, 0.f);

    // ldmatrix lane addressing
    int a_row = (lane & 7) + 8 * ((lane >> 3) & 1);
    int a_col8 = 8 * (lane >> 4);
    int b_row = lane & 15;

    #pragma unroll
    for (int ks = 0; ks < DD / 16; ks++) {
        int kb = ks * 16;
        uint32_t a[2][4];
        #pragma unroll
        for (int mt = 0; mt < 2; mt++) {
            uint32_t addr = smem_u32(As + (m0 + mt * 16 + a_row) * APH + kb + a_col8);
            ldmatrix_x4(a[mt][0], a[mt][1], a[mt][2], a[mt][3], addr);
        }
        uint32_t b[4][2];
        #pragma unroll
        for (int nt = 0; nt < 4; nt++) {
            int nbf = nb + nt * 8;
            uint32_t addr = smem_u32(Ws + (kb + b_row) * WPH + nbf);
            ldmatrix_x2_trans(b[nt][0], b[nt][1], addr);
        }
        #pragma unroll
        for (int mt = 0; mt < 2; mt++)
            #pragma unroll
            for (int nt = 0; nt < 4; nt++)
                mma_f16(c[mt][nt], a[mt][0], a[mt][1], a[mt][2], a[mt][3],
                        b[nt][0], b[nt][1]);
    }

    // epilogue: scale by dinv[row], write half2 pairs
    #pragma unroll
    for (int mt = 0; mt < 2; mt++) {
        int ra = row0 + m0 + mt * 16 + qid;
        int rb = ra + 8;
        float dva = (ra < NN) ? g_dinv[ra] : 0.f;
        float dvb = (rb < NN) ? g_dinv[rb] : 0.f;
        #pragma unroll
        for (int nt = 0; nt < 4; nt++) {
            int col = nb + nt * 8 + 2 * tq;
            if (ra < NN) {
                __half2 o = __floats2half2_rn(c[mt][nt].x * dva, c[mt][nt].y * dva);
                *(uint32_t*)(tout + (size_t)ra * DD + col) = *(uint32_t*)&o;
            }
            if (rb < NN) {
                __half2 o = __floats2half2_rn(c[mt][nt].z * dvb, c[mt][nt].w * dvb);
                *(uint32_t*)(tout + (size_t)rb * DD + col) = *(uint32_t*)&o;
            }
        }
    }
}

// ---------------- per-node gather accumulate (fp16 messages -> fp32 out) -------
// out[i] = b + dinv[i]*(tin[i] + sum_{e in CSR[i]} tin[src_e]) (+ res[i])
__global__ void __launch_bounds__(256) k_accum(const __half* __restrict__ tin,
                        float* __restrict__ out,
                        const float* __restrict__ b,
                        const float* __restrict__ res) {
    int node = (blockIdx.x * blockDim.x + threadIdx.x) >> 5;
    int lane = threadIdx.x & 31;
    if (node >= NN) return;

    const uint2* T = (const uint2*)tin;   // 4 halves per lane
    int s0 = g_start[node];
    int cnt = g_cnt[node];

    float4 a[8];
    {
        uint2 u = T[(size_t)node * 32 + lane];
        float2 f0 = __half22float2(*(__half2*)&u.x);
        float2 f1 = __half22float2(*(__half2*)&u.y);
        a[0] = make_float4(f0.x, f0.y, f1.x, f1.y);
    }
    #pragma unroll
    for (int j = 1; j < 8; j++) a[j] = make_float4(0.f, 0.f, 0.f, 0.f);

    int e = 0;
    for (; e + 8 <= cnt; e += 8) {
        int idx[8];
        #pragma unroll
        for (int j = 0; j < 8; j++) idx[j] = g_esrc[s0 + e + j];
        #pragma unroll
        for (int j = 0; j < 8; j++) {
            uint2 u = T[(size_t)idx[j] * 32 + lane];
            float2 f0 = __half22float2(*(__half2*)&u.x);
            float2 f1 = __half22float2(*(__half2*)&u.y);
            a[j].x += f0.x; a[j].y += f0.y; a[j].z += f1.x; a[j].w += f1.y;
        }
    }
    for (; e < cnt; e++) {
        int i0 = g_esrc[s0 + e];
        uint2 u = T[(size_t)i0 * 32 + lane];
        float2 f0 = __half22float2(*(__half2*)&u.x);
        float2 f1 = __half22float2(*(__half2*)&u.y);
        a[0].x += f0.x; a[0].y += f0.y; a[0].z += f1.x; a[0].w += f1.y;
    }
    #pragma unroll
    for (int j = 1; j < 8; j++) {
        a[0].x += a[j].x; a[0].y += a[j].y; a[0].z += a[j].z; a[0].w += a[j].w;
    }

    float dv = g_dinv[node];
    float4 bb = ((const float4*)b)[lane];
    float4 o;
    o.x = fmaf(dv, a[0].x, bb.x);
    o.y = fmaf(dv, a[0].y, bb.y);
    o.z = fmaf(dv, a[0].z, bb.z);
    o.w = fmaf(dv, a[0].w, bb.w);
    if (res) {
        float4 r = ((const float4*)(res))[(size_t)node * 32 + lane];
        o.x += r.x; o.y += r.y; o.z += r.z; o.w += r.w;
    }
    ((float4*)out)[(size_t)node * 32 + lane] = o;
}

// ---------------- launch ------------------------------------------------------
extern "C" void kernel_launch(void* const* d_in, const int* in_sizes, int n_in,
                              void* d_out, int out_size) {
    const float* x   = (const float*)d_in[0];
    const int*   ei  = (const int*)d_in[1];
    const int*   src = ei;
    const int*   dst = ei + EE;
    const float* lng0 = (const float*)d_in[2];
    const float* lnb0 = (const float*)d_in[3];
    const float* W0   = (const float*)d_in[4];
    const float* b0   = (const float*)d_in[5];
    const float* lng1 = (const float*)d_in[6];
    const float* lnb1 = (const float*)d_in[7];
    const float* W1   = (const float*)d_in[8];
    const float* b1   = (const float*)d_in[9];
    const float* lng2 = (const float*)d_in[10];
    const float* lnb2 = (const float*)d_in[11];
    const float* W2   = (const float*)d_in[12];
    const float* b2   = (const float*)d_in[13];
    float* out = (float*)d_out;

    __half* d_tA; cudaGetSymbolAddress((void**)&d_tA, g_tmpA);
    __half* d_tB; cudaGetSymbolAddress((void**)&d_tB, g_tmpB);
    float*  d_x1; cudaGetSymbolAddress((void**)&d_x1, g_x1);
    float*  d_h2; cudaGetSymbolAddress((void**)&d_h2, g_h2);
    __half* d_W16base; cudaGetSymbolAddress((void**)&d_W16base, g_W16);
    __half* d_Wa = d_W16base;
    __half* d_Wb = d_W16base + DD * DD;
    __half* d_Wc = d_W16base + 2 * DD * DD;

    cudaFuncSetAttribute(k_ln_gemm, cudaFuncAttributeMaxDynamicSharedMemorySize, SMEM_BYTES);

    const int gemm_blocks = (NN + BM - 1) / BM;   // 391
    const int acc_blocks = (NN * 32 + 255) / 256;

    // prep: weights + zero (merged), hist, dinv+chunk sums
    k_prep0<<<(NN + 255) / 256, 256>>>(W0, W1, W2);
    k_hist<<<(EE + 255) / 256, 256>>>(dst);
    k_scan_a<<<SNB, SCH>>>();

    // layer 0 GEMM (launch #4 -> ncu profile slot): x -> tA
    k_ln_gemm<<<gemm_blocks, 512, SMEM_BYTES>>>(x, lng0, lnb0, d_Wa, d_tA);

    // prep part 2 (CSR for accum)
    k_scan_c<<<SNB, SCH>>>();
    k_bucket<<<(EE + 255) / 256, 256>>>(src, dst);

    // layer 0 accum: tA (+x) -> x1
    k_accum<<<acc_blocks, 256>>>(d_tA, d_x1, b0, x);

    // layer 1: x1 -> tB ; accum -> h2
    k_ln_gemm<<<gemm_blocks, 512, SMEM_BYTES>>>(d_x1, lng1, lnb1, d_Wb, d_tB);
    k_accum<<<acc_blocks, 256>>>(d_tB, d_h2, b1, nullptr);

    // layer 2: h2 -> tA ; accum (+x1) -> out
    k_ln_gemm<<<gemm_blocks, 512, SMEM_BYTES>>>(d_h2, lng2, lnb2, d_Wc, d_tA);
    k_accum<<<acc_blocks, 256>>>(d_tA, out, b2, d_x1);
}